// round 13
// baseline (speedup 1.0000x reference)
#include <cuda_runtime.h>
#include <cuda_fp16.h>
#include <cstdint>

// SpatialConv implicit GEMM, fp16 mma.sync.m16n8k16 (f32 accum).
// Fragment-packed smem: A frag = 1 LDS.128, B frag = 1 LDS.64.
// 3-stage cp.async pipeline. CTA: 128 Co x 256 px (4 rows), 512 thr,
// 16 warps (4m x 4n), warp 32x64. Fused coalesced prep kernel.
// taps: 0:(0,0) 1:(-1,0) 2:(0,-1) 3:(0,1) 4:(1,0)

#define CI 256
#define CO 256
#define HH 64
#define WW 64
#define NB 16
#define NTH 512
#define NCHK 16
#define A_ST 5120            // u32 per A stage: [tap5][blk8][gid8][tig4][j4]
#define X_ST 3456            // u32 per X stage: [row6][col72][s8]
#define NSTG 3
#define DYN ((NSTG * (A_ST + X_ST)) * 4)   // 102912 B

// g_wti: [cob2][chk16][tap5][blk8][gid8][tig4][j4] u32 (fragment-packed half2)
__device__ __align__(16) uint32_t g_wti[163840];
// g_x2: [n16][chk16][h64][w64][s8] u32 ; s: cp_local = (s>>1)+(s&1)*4
__device__ __align__(16) uint32_t g_x2[(size_t)NB * 16 * HH * WW * 8];

#define XBLKS (NB * 16 * HH)    // 16384
#define WBLKS 640

__global__ void prep(const float* __restrict__ x, const float* __restrict__ wt) {
    if (blockIdx.x < XBLKS) {
        // x-pack: one block per (n, chk, h); coalesced read + coalesced write
        __shared__ float sx[16][65];
        int b = blockIdx.x;
        int h = b & 63, chk = (b >> 6) & 15, n = b >> 10;
        int t = threadIdx.x;
#pragma unroll
        for (int i = 0; i < 4; i++) {
            int c = (t >> 6) + i * 4, w = t & 63;
            sx[c][w] = x[(((size_t)n * CI + chk * 16 + c) * HH + h) * WW + w];
        }
        __syncthreads();
#pragma unroll
        for (int i = 0; i < 2; i++) {
            int o = t + i * 256;              // 0..511
            int w = o >> 3, s = o & 7;
            int cp = (s >> 1) + (s & 1) * 4;  // cp_local
            __half2 v = __floats2half2_rn(sx[2 * cp][w], sx[2 * cp + 1][w]);
            g_x2[((((size_t)(n * 16 + chk) * HH + h) * WW + w) << 3) + s] = *(uint32_t*)&v;
        }
    } else {
        // w-pack (fragment order identical to R12)
        int idx = (int)(blockIdx.x - XBLKS) * 256 + threadIdx.x;
        if (idx >= 163840) return;
        int j   = idx & 3, tig = (idx >> 2) & 3, gid = (idx >> 4) & 7;
        int blk = (idx >> 7) & 7, tap = (idx >> 10) % 5;
        int rest = idx / (5 << 10);
        int chk = rest & 15, cob = rest >> 4;
        int o  = cob * 128 + blk * 16 + gid + (j & 1) * 8;
        int cp = chk * 8 + tig + (j >> 1) * 4;
        float a = wt[(size_t)o * 1280 + (2 * cp) * 5 + tap];
        float bb = wt[(size_t)o * 1280 + (2 * cp + 1) * 5 + tap];
        __half2 hv = __floats2half2_rn(a, bb);
        g_wti[idx] = *(uint32_t*)&hv;
    }
}

__device__ __forceinline__ void cpa16(uint32_t dst, const void* src, int srcsz) {
    asm volatile("cp.async.cg.shared.global [%0], [%1], 16, %2;"
                 :: "r"(dst), "l"(src), "r"(srcsz));
}

__global__ __launch_bounds__(NTH, 1)
void conv_mma_kernel(float* __restrict__ out)
{
    extern __shared__ uint32_t sm[];
    const int tid  = threadIdx.x;
    const int lane = tid & 31, wid = tid >> 5;
    const int wm   = wid >> 2;      // 0..3 : 32-co tile
    const int wn   = wid & 3;       // 0..3 : output row
    const int gid  = lane >> 2, tig = lane & 3;
    const int cbi  = blockIdx.x;
    const int cob  = cbi * 128;
    const int h0   = blockIdx.y * 4;
    const int n    = blockIdx.z;

    uint32_t* Abuf = sm;
    uint32_t* Xbuf = sm + NSTG * A_ST;
    const uint32_t smB = (uint32_t)__cvta_generic_to_shared(sm);
    const uint32_t aB  = smB;
    const uint32_t xB  = smB + NSTG * A_ST * 4;

    // zero X border cols (0..3, 68..71) for 6 rows, all stages
    for (int e = tid; e < NSTG * 6 * 8 * 8; e += NTH) {
        int st = e / 384, r2 = e % 384;
        int r = r2 >> 6, cq = (r2 >> 3) & 7, s = r2 & 7;
        int col = (cq < 4) ? cq : (64 + cq);
        Xbuf[st * X_ST + r * 576 + col * 8 + s] = 0;
    }

    float acc[2][8][4];
#pragma unroll
    for (int mi = 0; mi < 2; mi++)
#pragma unroll
        for (int ni = 0; ni < 8; ni++)
#pragma unroll
            for (int r = 0; r < 4; r++) acc[mi][ni][r] = 0.f;

    auto stage = [&](int chk, int st) {
        // A: 5120 u32 contiguous -> 1280 x 16B
        const uint32_t* asrc = g_wti + ((size_t)(cbi * 16 + chk) * A_ST);
#pragma unroll
        for (int i = 0; i < 3; i++) {
            int e = tid + i * NTH;
            if (e < 1280)
                cpa16(aB + (uint32_t)((st * A_ST + e * 4) * 4), asrc + e * 4, 16);
        }
        // X: 6 rows (h0-1..h0+4), each 64 px x 32B contiguous -> 128 x 16B
#pragma unroll
        for (int i = 0; i < 2; i++) {
            int e = tid + i * NTH;
            if (e < 768) {
                int r = e >> 7, k = e & 127;
                int gh = h0 - 1 + r;
                int ok = ((unsigned)gh < HH) ? 16 : 0;
                int ghc = ok ? gh : 0;
                cpa16(xB + (uint32_t)((st * X_ST + r * 576 + 32 + k * 4) * 4),
                      g_x2 + ((((size_t)(n * 16 + chk) * HH + ghc) * WW) * 8 + k * 4), ok);
            }
        }
    };

    stage(0, 0);
    asm volatile("cp.async.commit_group;");
    stage(1, 1);
    asm volatile("cp.async.commit_group;");

    const int ROW[5] = {1, 0, 1, 1, 2};
    const int DX5[5] = {0, 0, -1, 1, 0};

    for (int chk = 0; chk < NCHK; chk++) {
        const int st = chk % NSTG;
        asm volatile("cp.async.wait_group 1;");
        __syncthreads();

        if (chk + 2 < NCHK) stage(chk + 2, (chk + 2) % NSTG);
        asm volatile("cp.async.commit_group;");

        const uint32_t* A = Abuf + st * A_ST;
        const uint32_t* X = Xbuf + st * X_ST;

#pragma unroll
        for (int tap = 0; tap < 5; tap++) {
            const int rr = ROW[tap] + wn;
            const int dx = DX5[tap];

            uint32_t a[2][4], b[8][2];
#pragma unroll
            for (int mi = 0; mi < 2; mi++) {
                int blk = 2 * wm + mi;
                uint4 v = *(const uint4*)&A[(tap * 8 + blk) * 128 + gid * 16 + tig * 4];
                a[mi][0] = v.x; a[mi][1] = v.y; a[mi][2] = v.z; a[mi][3] = v.w;
            }
#pragma unroll
            for (int ni = 0; ni < 8; ni++) {
                int col = ni * 8 + gid + 4 + dx;
                uint2 v = *(const uint2*)&X[rr * 576 + col * 8 + tig * 2];
                b[ni][0] = v.x; b[ni][1] = v.y;
            }
#pragma unroll
            for (int mi = 0; mi < 2; mi++)
#pragma unroll
                for (int ni = 0; ni < 8; ni++) {
                    asm volatile(
                        "mma.sync.aligned.m16n8k16.row.col.f32.f16.f16.f32 "
                        "{%0,%1,%2,%3}, {%4,%5,%6,%7}, {%8,%9}, {%0,%1,%2,%3};"
                        : "+f"(acc[mi][ni][0]), "+f"(acc[mi][ni][1]),
                          "+f"(acc[mi][ni][2]), "+f"(acc[mi][ni][3])
                        : "r"(a[mi][0]), "r"(a[mi][1]), "r"(a[mi][2]), "r"(a[mi][3]),
                          "r"(b[ni][0]), "r"(b[ni][1]));
                }
        }
    }

    // epilogue: warp wn owns row h0+wn
    const int h = h0 + wn;
#pragma unroll
    for (int mi = 0; mi < 2; mi++) {
        int co0 = cob + wm * 32 + mi * 16 + gid;
#pragma unroll
        for (int ni = 0; ni < 8; ni++) {
            int c0 = ni * 8 + tig * 2;
            *(float2*)&out[(((size_t)n * CO + co0) * HH + h) * WW + c0] =
                make_float2(acc[mi][ni][0], acc[mi][ni][1]);
            *(float2*)&out[(((size_t)n * CO + co0 + 8) * HH + h) * WW + c0] =
                make_float2(acc[mi][ni][2], acc[mi][ni][3]);
        }
    }
}

extern "C" void kernel_launch(void* const* d_in, const int* in_sizes, int n_in,
                              void* d_out, int out_size)
{
    const float* x  = (const float*)d_in[0];
    const float* wt = (const float*)d_in[1];
    float* out = (float*)d_out;

    prep<<<XBLKS + WBLKS, 256>>>(x, wt);

    cudaFuncSetAttribute(conv_mma_kernel,
                         cudaFuncAttributeMaxDynamicSharedMemorySize, DYN);
    dim3 grid(CO / 128, HH / 4, NB);   // (2, 16, 16) = 512 CTAs
    conv_mma_kernel<<<grid, NTH, DYN>>>(out);
}

// round 14
// speedup vs baseline: 1.2295x; 1.2295x over previous
#include <cuda_runtime.h>
#include <cuda_fp16.h>
#include <cstdint>

// SpatialConv implicit GEMM, fp16 mma.sync.m16n8k16 (f32 accum).
// Fragment-packed smem: A frag = 1 LDS.128, B frag = 1 LDS.64.
// 3-stage cp.async pipeline. CTA: 128 Co x 128 px (2 rows), 256 thr,
// 8 warps (4m x 2n), warp 32x64, 2 CTAs/SM. Warp-transpose prep (no smem).
// taps: 0:(0,0) 1:(-1,0) 2:(0,-1) 3:(0,1) 4:(1,0)

#define CI 256
#define CO 256
#define HH 64
#define WW 64
#define NB 16
#define NTH 256
#define NCHK 16
#define A_ST 5120            // u32 per A stage: [tap5][blk8][gid8][tig4][j4]
#define X_ST 2304            // u32 per X stage: [row4][col72][s8]
#define NSTG 3
#define DYN ((NSTG * (A_ST + X_ST)) * 4)   // 89088 B

// g_wti: [cob2][chk16][tap5][blk8][gid8][tig4][j4] u32 (fragment-packed half2)
__device__ __align__(16) uint32_t g_wti[163840];
// g_x2: [n16][chk16][h64][w64][s8] u32 ; s -> cp_local = (s>>1)+(s&1)*4
__device__ __align__(16) uint32_t g_x2[(size_t)NB * 16 * HH * WW * 8];

#define XWARPS (NB * 16 * HH)            // 16384 warps, 8 per 256-thr block
#define XBLKS (XWARPS / 8)               // 2048
#define WBLKS 640

__global__ void prep(const float* __restrict__ x, const float* __restrict__ wt) {
    if (blockIdx.x < XBLKS) {
        // one warp per (n, chk, h)
        int gw = blockIdx.x * 8 + (threadIdx.x >> 5);   // global warp id
        int lane = threadIdx.x & 31;
        int h = gw & 63, chk = (gw >> 6) & 15, n = gw >> 10;
        const float* xb = x + (((size_t)n * CI + chk * 16) * HH + h) * WW;
#pragma unroll
        for (int half = 0; half < 2; half++) {
            int w = half * 32 + lane;
            float v[16];
#pragma unroll
            for (int c = 0; c < 16; c++)
                v[c] = xb[(size_t)c * HH * WW + w];   // coalesced per c
            uint32_t p[8];
#pragma unroll
            for (int s = 0; s < 8; s++) {
                int cp = (s >> 1) + (s & 1) * 4;
                __half2 hv = __floats2half2_rn(v[2 * cp], v[2 * cp + 1]);
                p[s] = *(uint32_t*)&hv;
            }
            uint32_t* dst = g_x2 + ((((size_t)(n * 16 + chk) * HH + h) * WW + w) << 3);
            *(uint4*)dst       = make_uint4(p[0], p[1], p[2], p[3]);
            *(uint4*)(dst + 4) = make_uint4(p[4], p[5], p[6], p[7]);
        }
    } else {
        int idx = (int)(blockIdx.x - XBLKS) * 256 + threadIdx.x;
        if (idx >= 163840) return;
        int j   = idx & 3, tig = (idx >> 2) & 3, gid = (idx >> 4) & 7;
        int blk = (idx >> 7) & 7, tap = (idx >> 10) % 5;
        int rest = idx / (5 << 10);
        int chk = rest & 15, cob = rest >> 4;
        int o  = cob * 128 + blk * 16 + gid + (j & 1) * 8;
        int cp = chk * 8 + tig + (j >> 1) * 4;
        float a = wt[(size_t)o * 1280 + (2 * cp) * 5 + tap];
        float bb = wt[(size_t)o * 1280 + (2 * cp + 1) * 5 + tap];
        __half2 hv = __floats2half2_rn(a, bb);
        g_wti[idx] = *(uint32_t*)&hv;
    }
}

__device__ __forceinline__ void cpa16(uint32_t dst, const void* src, int srcsz) {
    asm volatile("cp.async.cg.shared.global [%0], [%1], 16, %2;"
                 :: "r"(dst), "l"(src), "r"(srcsz));
}

__global__ __launch_bounds__(NTH, 2)
void conv_mma_kernel(float* __restrict__ out)
{
    extern __shared__ uint32_t sm[];
    const int tid  = threadIdx.x;
    const int lane = tid & 31, wid = tid >> 5;
    const int wm   = wid >> 1;      // 0..3 : 32-co tile
    const int wn   = wid & 1;       // 0..1 : output row
    const int gid  = lane >> 2, tig = lane & 3;
    const int cbi  = blockIdx.x;
    const int cob  = cbi * 128;
    const int h0   = blockIdx.y * 2;
    const int n    = blockIdx.z;

    uint32_t* Abuf = sm;
    uint32_t* Xbuf = sm + NSTG * A_ST;
    const uint32_t smB = (uint32_t)__cvta_generic_to_shared(sm);
    const uint32_t aB  = smB;
    const uint32_t xB  = smB + NSTG * A_ST * 4;

    // zero X border cols (0..3, 68..71) for 4 rows, all stages
    for (int e = tid; e < NSTG * 4 * 8 * 8; e += NTH) {
        int st = e / 256, r2 = e & 255;
        int r = r2 >> 6, cq = (r2 >> 3) & 7, s = r2 & 7;
        int col = (cq < 4) ? cq : (64 + cq);
        Xbuf[st * X_ST + r * 576 + col * 8 + s] = 0;
    }

    float acc[2][8][4];
#pragma unroll
    for (int mi = 0; mi < 2; mi++)
#pragma unroll
        for (int ni = 0; ni < 8; ni++)
#pragma unroll
            for (int r = 0; r < 4; r++) acc[mi][ni][r] = 0.f;

    auto stage = [&](int chk, int st) {
        const uint32_t* asrc = g_wti + ((size_t)(cbi * 16 + chk) * A_ST);
#pragma unroll
        for (int i = 0; i < 5; i++) {
            int e = tid + i * NTH;
            cpa16(aB + (uint32_t)((st * A_ST + e * 4) * 4), asrc + e * 4, 16);
        }
#pragma unroll
        for (int i = 0; i < 2; i++) {
            int e = tid + i * NTH;
            int r = e >> 7, k = e & 127;
            int gh = h0 - 1 + r;
            int ok = ((unsigned)gh < HH) ? 16 : 0;
            int ghc = ok ? gh : 0;
            cpa16(xB + (uint32_t)((st * X_ST + r * 576 + 32 + k * 4) * 4),
                  g_x2 + ((((size_t)(n * 16 + chk) * HH + ghc) * WW) * 8 + k * 4), ok);
        }
    };

    stage(0, 0);
    asm volatile("cp.async.commit_group;");
    stage(1, 1);
    asm volatile("cp.async.commit_group;");

    const int ROW[5] = {1, 0, 1, 1, 2};
    const int DX5[5] = {0, 0, -1, 1, 0};

    for (int chk = 0; chk < NCHK; chk++) {
        const int st = chk % NSTG;
        asm volatile("cp.async.wait_group 1;");
        __syncthreads();

        if (chk + 2 < NCHK) stage(chk + 2, (chk + 2) % NSTG);
        asm volatile("cp.async.commit_group;");

        const uint32_t* A = Abuf + st * A_ST;
        const uint32_t* X = Xbuf + st * X_ST;

#pragma unroll
        for (int tap = 0; tap < 5; tap++) {
            const int rr = ROW[tap] + wn;
            const int dx = DX5[tap];

            uint32_t a[2][4], b[8][2];
#pragma unroll
            for (int mi = 0; mi < 2; mi++) {
                int blk = 2 * wm + mi;
                uint4 v = *(const uint4*)&A[(tap * 8 + blk) * 128 + gid * 16 + tig * 4];
                a[mi][0] = v.x; a[mi][1] = v.y; a[mi][2] = v.z; a[mi][3] = v.w;
            }
#pragma unroll
            for (int ni = 0; ni < 8; ni++) {
                int col = ni * 8 + gid + 4 + dx;
                uint2 v = *(const uint2*)&X[rr * 576 + col * 8 + tig * 2];
                b[ni][0] = v.x; b[ni][1] = v.y;
            }
#pragma unroll
            for (int mi = 0; mi < 2; mi++)
#pragma unroll
                for (int ni = 0; ni < 8; ni++) {
                    asm volatile(
                        "mma.sync.aligned.m16n8k16.row.col.f32.f16.f16.f32 "
                        "{%0,%1,%2,%3}, {%4,%5,%6,%7}, {%8,%9}, {%0,%1,%2,%3};"
                        : "+f"(acc[mi][ni][0]), "+f"(acc[mi][ni][1]),
                          "+f"(acc[mi][ni][2]), "+f"(acc[mi][ni][3])
                        : "r"(a[mi][0]), "r"(a[mi][1]), "r"(a[mi][2]), "r"(a[mi][3]),
                          "r"(b[ni][0]), "r"(b[ni][1]));
                }
        }
    }

    // epilogue: warp wn owns row h0+wn
    const int h = h0 + wn;
#pragma unroll
    for (int mi = 0; mi < 2; mi++) {
        int co0 = cob + wm * 32 + mi * 16 + gid;
#pragma unroll
        for (int ni = 0; ni < 8; ni++) {
            int c0 = ni * 8 + tig * 2;
            *(float2*)&out[(((size_t)n * CO + co0) * HH + h) * WW + c0] =
                make_float2(acc[mi][ni][0], acc[mi][ni][1]);
            *(float2*)&out[(((size_t)n * CO + co0 + 8) * HH + h) * WW + c0] =
                make_float2(acc[mi][ni][2], acc[mi][ni][3]);
        }
    }
}

extern "C" void kernel_launch(void* const* d_in, const int* in_sizes, int n_in,
                              void* d_out, int out_size)
{
    const float* x  = (const float*)d_in[0];
    const float* wt = (const float*)d_in[1];
    float* out = (float*)d_out;

    prep<<<XBLKS + WBLKS, 256>>>(x, wt);

    cudaFuncSetAttribute(conv_mma_kernel,
                         cudaFuncAttributeMaxDynamicSharedMemorySize, DYN);
    dim3 grid(CO / 128, HH / 2, NB);   // (2, 32, 16) = 1024 CTAs
    conv_mma_kernel<<<grid, NTH, DYN>>>(out);
}

// round 15
// speedup vs baseline: 1.2337x; 1.0034x over previous
#include <cuda_runtime.h>
#include <cuda_fp16.h>
#include <cstdint>

// SpatialConv implicit GEMM, fp16 mma.sync.m16n8k16 (f32 accum).
// A fragments loaded DIRECTLY from gmem (fragment-packed, LDG.128, rolling
// tap-ahead prefetch) -> A never touches the smem crossbar.
// X staged via 3-stage cp.async, B frag = 1 LDS.64.
// CTA: 128 Co x 128 px (2 rows), 256 thr, 8 warps (4m x 2n), warp 32x64.
// taps: 0:(0,0) 1:(-1,0) 2:(0,-1) 3:(0,1) 4:(1,0)

#define CI 256
#define CO 256
#define HH 64
#define WW 64
#define NB 16
#define NTH 256
#define NCHK 16
#define X_ST 2304            // u32 per X stage: [row4][col72][s8]
#define NSTG 3
#define DYN ((NSTG * X_ST) * 4)   // 27648 B

// g_wti: [cob2][chk16][tap5][blk8][gid8][tig4][j4] u32 (fragment-packed half2)
__device__ __align__(16) uint32_t g_wti[163840];
// g_x2: [n16][chk16][h64][w64][s8] u32 ; s -> cp_local = (s>>1)+(s&1)*4
__device__ __align__(16) uint32_t g_x2[(size_t)NB * 16 * HH * WW * 8];

#define XWARPS (NB * 16 * HH)            // 16384 warps, 8 per block
#define XBLKS (XWARPS / 8)               // 2048
#define WBLKS 640

__global__ void prep(const float* __restrict__ x, const float* __restrict__ wt) {
    if (blockIdx.x < XBLKS) {
        int gw = blockIdx.x * 8 + (threadIdx.x >> 5);
        int lane = threadIdx.x & 31;
        int h = gw & 63, chk = (gw >> 6) & 15, n = gw >> 10;
        const float* xb = x + (((size_t)n * CI + chk * 16) * HH + h) * WW;
#pragma unroll
        for (int half = 0; half < 2; half++) {
            int w = half * 32 + lane;
            float v[16];
#pragma unroll
            for (int c = 0; c < 16; c++)
                v[c] = xb[(size_t)c * HH * WW + w];
            uint32_t p[8];
#pragma unroll
            for (int s = 0; s < 8; s++) {
                int cp = (s >> 1) + (s & 1) * 4;
                __half2 hv = __floats2half2_rn(v[2 * cp], v[2 * cp + 1]);
                p[s] = *(uint32_t*)&hv;
            }
            uint32_t* dst = g_x2 + ((((size_t)(n * 16 + chk) * HH + h) * WW + w) << 3);
            *(uint4*)dst       = make_uint4(p[0], p[1], p[2], p[3]);
            *(uint4*)(dst + 4) = make_uint4(p[4], p[5], p[6], p[7]);
        }
    } else {
        int idx = (int)(blockIdx.x - XBLKS) * 256 + threadIdx.x;
        if (idx >= 163840) return;
        int j   = idx & 3, tig = (idx >> 2) & 3, gid = (idx >> 4) & 7;
        int blk = (idx >> 7) & 7, tap = (idx >> 10) % 5;
        int rest = idx / (5 << 10);
        int chk = rest & 15, cob = rest >> 4;
        int o  = cob * 128 + blk * 16 + gid + (j & 1) * 8;
        int cp = chk * 8 + tig + (j >> 1) * 4;
        float a = wt[(size_t)o * 1280 + (2 * cp) * 5 + tap];
        float bb = wt[(size_t)o * 1280 + (2 * cp + 1) * 5 + tap];
        __half2 hv = __floats2half2_rn(a, bb);
        g_wti[idx] = *(uint32_t*)&hv;
    }
}

__device__ __forceinline__ void cpa16(uint32_t dst, const void* src, int srcsz) {
    asm volatile("cp.async.cg.shared.global [%0], [%1], 16, %2;"
                 :: "r"(dst), "l"(src), "r"(srcsz));
}

__global__ __launch_bounds__(NTH, 2)
void conv_mma_kernel(float* __restrict__ out)
{
    extern __shared__ uint32_t sm[];
    const int tid  = threadIdx.x;
    const int lane = tid & 31, wid = tid >> 5;
    const int wm   = wid >> 1;      // 0..3 : 32-co tile
    const int wn   = wid & 1;       // 0..1 : output row
    const int gid  = lane >> 2, tig = lane & 3;
    const int cbi  = blockIdx.x;
    const int cob  = cbi * 128;
    const int h0   = blockIdx.y * 2;
    const int n    = blockIdx.z;

    uint32_t* Xbuf = sm;
    const uint32_t xB = (uint32_t)__cvta_generic_to_shared(sm);

    // per-thread constant part of A-fragment offset
    const uint32_t* aptr = g_wti + (size_t)cbi * 81920 + gid * 16 + tig * 4;
    // frag offset(chk, tap, mi): chk*5120 + tap*1024 + (2*wm+mi)*128

    // zero X border cols (0..3, 68..71) for 4 rows, all stages
    for (int e = tid; e < NSTG * 4 * 8 * 8; e += NTH) {
        int st = e / 256, r2 = e & 255;
        int r = r2 >> 6, cq = (r2 >> 3) & 7, s = r2 & 7;
        int col = (cq < 4) ? cq : (64 + cq);
        Xbuf[st * X_ST + r * 576 + col * 8 + s] = 0;
    }

    float acc[2][8][4];
#pragma unroll
    for (int mi = 0; mi < 2; mi++)
#pragma unroll
        for (int ni = 0; ni < 8; ni++)
#pragma unroll
            for (int r = 0; r < 4; r++) acc[mi][ni][r] = 0.f;

    auto stageX = [&](int chk, int st) {
#pragma unroll
        for (int i = 0; i < 2; i++) {
            int e = tid + i * NTH;
            int r = e >> 7, k = e & 127;
            int gh = h0 - 1 + r;
            int ok = ((unsigned)gh < HH) ? 16 : 0;
            int ghc = ok ? gh : 0;
            cpa16(xB + (uint32_t)((st * X_ST + r * 576 + 32 + k * 4) * 4),
                  g_x2 + ((((size_t)(n * 16 + chk) * HH + ghc) * WW) * 8 + k * 4), ok);
        }
    };

    stageX(0, 0);
    asm volatile("cp.async.commit_group;");
    stageX(1, 1);
    asm volatile("cp.async.commit_group;");

    const int ROW[5] = {1, 0, 1, 1, 2};
    const int DX5[5] = {0, 0, -1, 1, 0};

    // prologue: load A frags for (chk=0, tap=0)
    uint32_t acur[2][4], anxt[2][4];
#pragma unroll
    for (int mi = 0; mi < 2; mi++) {
        uint4 v = *(const uint4*)&aptr[(2 * wm + mi) * 128];
        acur[mi][0] = v.x; acur[mi][1] = v.y; acur[mi][2] = v.z; acur[mi][3] = v.w;
    }

    for (int chk = 0; chk < NCHK; chk++) {
        const int st = chk % NSTG;
        asm volatile("cp.async.wait_group 1;");
        __syncthreads();

        if (chk + 2 < NCHK) stageX(chk + 2, (chk + 2) % NSTG);
        asm volatile("cp.async.commit_group;");

        const uint32_t* X = Xbuf + st * X_ST;

#pragma unroll
        for (int tap = 0; tap < 5; tap++) {
            // prefetch A frags for next step (tap+1, or next chunk's tap 0)
            {
                int cn = (tap == 4) ? ((chk + 1 < NCHK) ? chk + 1 : chk) : chk;
                int tn = (tap == 4) ? 0 : tap + 1;
#pragma unroll
                for (int mi = 0; mi < 2; mi++) {
                    uint4 v = *(const uint4*)&aptr[cn * 5120 + tn * 1024 + (2 * wm + mi) * 128];
                    anxt[mi][0] = v.x; anxt[mi][1] = v.y; anxt[mi][2] = v.z; anxt[mi][3] = v.w;
                }
            }

            const int rr = ROW[tap] + wn;
            const int dx = DX5[tap];
            uint32_t b[8][2];
#pragma unroll
            for (int ni = 0; ni < 8; ni++) {
                int col = ni * 8 + gid + 4 + dx;
                uint2 v = *(const uint2*)&X[rr * 576 + col * 8 + tig * 2];
                b[ni][0] = v.x; b[ni][1] = v.y;
            }
#pragma unroll
            for (int mi = 0; mi < 2; mi++)
#pragma unroll
                for (int ni = 0; ni < 8; ni++) {
                    asm volatile(
                        "mma.sync.aligned.m16n8k16.row.col.f32.f16.f16.f32 "
                        "{%0,%1,%2,%3}, {%4,%5,%6,%7}, {%8,%9}, {%0,%1,%2,%3};"
                        : "+f"(acc[mi][ni][0]), "+f"(acc[mi][ni][1]),
                          "+f"(acc[mi][ni][2]), "+f"(acc[mi][ni][3])
                        : "r"(acur[mi][0]), "r"(acur[mi][1]), "r"(acur[mi][2]), "r"(acur[mi][3]),
                          "r"(b[ni][0]), "r"(b[ni][1]));
                }
#pragma unroll
            for (int mi = 0; mi < 2; mi++)
#pragma unroll
                for (int j = 0; j < 4; j++) acur[mi][j] = anxt[mi][j];
        }
    }

    // epilogue: warp wn owns row h0+wn
    const int h = h0 + wn;
#pragma unroll
    for (int mi = 0; mi < 2; mi++) {
        int co0 = cob + wm * 32 + mi * 16 + gid;
#pragma unroll
        for (int ni = 0; ni < 8; ni++) {
            int c0 = ni * 8 + tig * 2;
            *(float2*)&out[(((size_t)n * CO + co0) * HH + h) * WW + c0] =
                make_float2(acc[mi][ni][0], acc[mi][ni][1]);
            *(float2*)&out[(((size_t)n * CO + co0 + 8) * HH + h) * WW + c0] =
                make_float2(acc[mi][ni][2], acc[mi][ni][3]);
        }
    }
}

extern "C" void kernel_launch(void* const* d_in, const int* in_sizes, int n_in,
                              void* d_out, int out_size)
{
    const float* x  = (const float*)d_in[0];
    const float* wt = (const float*)d_in[1];
    float* out = (float*)d_out;

    prep<<<XBLKS + WBLKS, 256>>>(x, wt);

    cudaFuncSetAttribute(conv_mma_kernel,
                         cudaFuncAttributeMaxDynamicSharedMemorySize, DYN);
    dim3 grid(CO / 128, HH / 2, NB);   // (2, 32, 16) = 1024 CTAs
    conv_mma_kernel<<<grid, NTH, DYN>>>(out);
}

// round 16
// speedup vs baseline: 1.2989x; 1.0529x over previous
#include <cuda_runtime.h>
#include <cuda_fp16.h>
#include <cstdint>

// SpatialConv implicit GEMM, fp16 mma.sync.m16n8k16 (f32 accum).
// A fragments loaded DIRECTLY from gmem (fragment-packed, LDG.128, rolling
// prefetch across 10 tap-steps). X staged via 3-stage cp.async, 32-channel
// chunks (8 chunks, 8 barriers). B frag = 1 LDS.64.
// CTA: 128 Co x 128 px (2 rows), 256 thr, 8 warps (4m x 2n), warp 32x64.
// taps: 0:(0,0) 1:(-1,0) 2:(0,-1) 3:(0,1) 4:(1,0)

#define CI 256
#define CO 256
#define HH 64
#define WW 64
#define NB 16
#define NTH 256
#define NCHK 8               // 32-channel chunks
#define X_SUB 2304           // u32 per 16-ch sub-block: [row4][col72][s8]
#define X_ST (2 * X_SUB)     // 4608 u32 per stage
#define NSTG 3
#define DYN ((NSTG * X_ST) * 4)   // 55296 B

// g_wti: [cob2][chk16][tap5][blk8][gid8][tig4][j4] u32 (fragment-packed half2)
__device__ __align__(16) uint32_t g_wti[163840];
// g_x2: [n16][chk16][h64][w64][s8] u32 ; s -> cp_local = (s>>1)+(s&1)*4
__device__ __align__(16) uint32_t g_x2[(size_t)NB * 16 * HH * WW * 8];

#define XWARPS (NB * 16 * HH)
#define XBLKS (XWARPS / 8)               // 2048
#define WBLKS 640

__global__ void prep(const float* __restrict__ x, const float* __restrict__ wt) {
    if (blockIdx.x < XBLKS) {
        int gw = blockIdx.x * 8 + (threadIdx.x >> 5);
        int lane = threadIdx.x & 31;
        int h = gw & 63, chk = (gw >> 6) & 15, n = gw >> 10;
        const float* xb = x + (((size_t)n * CI + chk * 16) * HH + h) * WW;
#pragma unroll
        for (int half = 0; half < 2; half++) {
            int w = half * 32 + lane;
            float v[16];
#pragma unroll
            for (int c = 0; c < 16; c++)
                v[c] = xb[(size_t)c * HH * WW + w];
            uint32_t p[8];
#pragma unroll
            for (int s = 0; s < 8; s++) {
                int cp = (s >> 1) + (s & 1) * 4;
                __half2 hv = __floats2half2_rn(v[2 * cp], v[2 * cp + 1]);
                p[s] = *(uint32_t*)&hv;
            }
            uint32_t* dst = g_x2 + ((((size_t)(n * 16 + chk) * HH + h) * WW + w) << 3);
            *(uint4*)dst       = make_uint4(p[0], p[1], p[2], p[3]);
            *(uint4*)(dst + 4) = make_uint4(p[4], p[5], p[6], p[7]);
        }
    } else {
        int idx = (int)(blockIdx.x - XBLKS) * 256 + threadIdx.x;
        if (idx >= 163840) return;
        int j   = idx & 3, tig = (idx >> 2) & 3, gid = (idx >> 4) & 7;
        int blk = (idx >> 7) & 7, tap = (idx >> 10) % 5;
        int rest = idx / (5 << 10);
        int chk = rest & 15, cob = rest >> 4;
        int o  = cob * 128 + blk * 16 + gid + (j & 1) * 8;
        int cp = chk * 8 + tig + (j >> 1) * 4;
        float a = wt[(size_t)o * 1280 + (2 * cp) * 5 + tap];
        float bb = wt[(size_t)o * 1280 + (2 * cp + 1) * 5 + tap];
        __half2 hv = __floats2half2_rn(a, bb);
        g_wti[idx] = *(uint32_t*)&hv;
    }
}

__device__ __forceinline__ void cpa16(uint32_t dst, const void* src, int srcsz) {
    asm volatile("cp.async.cg.shared.global [%0], [%1], 16, %2;"
                 :: "r"(dst), "l"(src), "r"(srcsz));
}

__global__ __launch_bounds__(NTH, 2)
void conv_mma_kernel(float* __restrict__ out)
{
    extern __shared__ uint32_t sm[];
    const int tid  = threadIdx.x;
    const int lane = tid & 31, wid = tid >> 5;
    const int wm   = wid >> 1;      // 0..3 : 32-co tile
    const int wn   = wid & 1;       // 0..1 : output row
    const int gid  = lane >> 2, tig = lane & 3;
    const int cbi  = blockIdx.x;
    const int cob  = cbi * 128;
    const int h0   = blockIdx.y * 2;
    const int n    = blockIdx.z;

    uint32_t* Xbuf = sm;
    const uint32_t xB = (uint32_t)__cvta_generic_to_shared(sm);

    // per-thread constant part of A-fragment address
    const uint32_t* aptr = g_wti + (size_t)cbi * 81920 + gid * 16 + tig * 4;
    // frag offset(sub16, tap, mi): sub16*5120 + tap*1024 + (2*wm+mi)*128

    // zero X border cols (0..3, 68..71): 2 subs x 4 rows per stage
    for (int e = tid; e < NSTG * 2 * 4 * 8 * 8; e += NTH) {
        int st = e / 512, r2 = e % 512;
        int sub = r2 >> 8, r = (r2 >> 6) & 3, cq = (r2 >> 3) & 7, s = r2 & 7;
        int col = (cq < 4) ? cq : (64 + cq);
        Xbuf[st * X_ST + sub * X_SUB + r * 576 + col * 8 + s] = 0;
    }

    float acc[2][8][4];
#pragma unroll
    for (int mi = 0; mi < 2; mi++)
#pragma unroll
        for (int ni = 0; ni < 8; ni++)
#pragma unroll
            for (int r = 0; r < 4; r++) acc[mi][ni][r] = 0.f;

    auto stageX = [&](int chk, int st) {
#pragma unroll
        for (int sub = 0; sub < 2; sub++) {
#pragma unroll
            for (int i = 0; i < 2; i++) {
                int e = tid + i * NTH;
                int r = e >> 7, k = e & 127;
                int gh = h0 - 1 + r;
                int ok = ((unsigned)gh < HH) ? 16 : 0;
                int ghc = ok ? gh : 0;
                cpa16(xB + (uint32_t)((st * X_ST + sub * X_SUB + r * 576 + 32 + k * 4) * 4),
                      g_x2 + ((((size_t)(n * 16 + chk * 2 + sub) * HH + ghc) * WW) * 8 + k * 4), ok);
            }
        }
    };

    stageX(0, 0);
    asm volatile("cp.async.commit_group;");
    stageX(1, 1);
    asm volatile("cp.async.commit_group;");

    const int ROW[5] = {1, 0, 1, 1, 2};
    const int DX5[5] = {0, 0, -1, 1, 0};

    // prologue: A frags for (sub16=0, tap=0)
    uint32_t acur[2][4], anxt[2][4];
#pragma unroll
    for (int mi = 0; mi < 2; mi++) {
        uint4 v = *(const uint4*)&aptr[(2 * wm + mi) * 128];
        acur[mi][0] = v.x; acur[mi][1] = v.y; acur[mi][2] = v.z; acur[mi][3] = v.w;
    }

    for (int chk = 0; chk < NCHK; chk++) {
        const int st = chk % NSTG;
        asm volatile("cp.async.wait_group 1;");
        __syncthreads();

        if (chk + 2 < NCHK) stageX(chk + 2, (chk + 2) % NSTG);
        asm volatile("cp.async.commit_group;");

        const uint32_t* Xs = Xbuf + st * X_ST;

#pragma unroll
        for (int kb = 0; kb < 10; kb++) {
            const int sub = (kb < 5) ? 0 : 1;
            const int tap = (kb < 5) ? kb : kb - 5;

            // prefetch A frags for next step
            {
                int kn = kb + 1;
                int cn = chk, sn = (kn < 5) ? 0 : 1, tn = (kn < 5) ? kn : kn - 5;
                if (kn == 10) { cn = (chk + 1 < NCHK) ? chk + 1 : chk; sn = 0; tn = 0; }
                int s16 = cn * 2 + sn;
#pragma unroll
                for (int mi = 0; mi < 2; mi++) {
                    uint4 v = *(const uint4*)&aptr[s16 * 5120 + tn * 1024 + (2 * wm + mi) * 128];
                    anxt[mi][0] = v.x; anxt[mi][1] = v.y; anxt[mi][2] = v.z; anxt[mi][3] = v.w;
                }
            }

            const int rr = ROW[tap] + wn;
            const int dx = DX5[tap];
            const uint32_t* X = Xs + sub * X_SUB;
            uint32_t b[8][2];
#pragma unroll
            for (int ni = 0; ni < 8; ni++) {
                int col = ni * 8 + gid + 4 + dx;
                uint2 v = *(const uint2*)&X[rr * 576 + col * 8 + tig * 2];
                b[ni][0] = v.x; b[ni][1] = v.y;
            }
#pragma unroll
            for (int mi = 0; mi < 2; mi++)
#pragma unroll
                for (int ni = 0; ni < 8; ni++) {
                    asm volatile(
                        "mma.sync.aligned.m16n8k16.row.col.f32.f16.f16.f32 "
                        "{%0,%1,%2,%3}, {%4,%5,%6,%7}, {%8,%9}, {%0,%1,%2,%3};"
                        : "+f"(acc[mi][ni][0]), "+f"(acc[mi][ni][1]),
                          "+f"(acc[mi][ni][2]), "+f"(acc[mi][ni][3])
                        : "r"(acur[mi][0]), "r"(acur[mi][1]), "r"(acur[mi][2]), "r"(acur[mi][3]),
                          "r"(b[ni][0]), "r"(b[ni][1]));
                }
#pragma unroll
            for (int mi = 0; mi < 2; mi++)
#pragma unroll
                for (int j = 0; j < 4; j++) acur[mi][j] = anxt[mi][j];
        }
    }

    // epilogue: warp wn owns row h0+wn
    const int h = h0 + wn;
#pragma unroll
    for (int mi = 0; mi < 2; mi++) {
        int co0 = cob + wm * 32 + mi * 16 + gid;
#pragma unroll
        for (int ni = 0; ni < 8; ni++) {
            int c0 = ni * 8 + tig * 2;
            *(float2*)&out[(((size_t)n * CO + co0) * HH + h) * WW + c0] =
                make_float2(acc[mi][ni][0], acc[mi][ni][1]);
            *(float2*)&out[(((size_t)n * CO + co0 + 8) * HH + h) * WW + c0] =
                make_float2(acc[mi][ni][2], acc[mi][ni][3]);
        }
    }
}

extern "C" void kernel_launch(void* const* d_in, const int* in_sizes, int n_in,
                              void* d_out, int out_size)
{
    const float* x  = (const float*)d_in[0];
    const float* wt = (const float*)d_in[1];
    float* out = (float*)d_out;

    prep<<<XBLKS + WBLKS, 256>>>(x, wt);

    cudaFuncSetAttribute(conv_mma_kernel,
                         cudaFuncAttributeMaxDynamicSharedMemorySize, DYN);
    dim3 grid(CO / 128, HH / 2, NB);   // (2, 32, 16) = 1024 CTAs
    conv_mma_kernel<<<grid, NTH, DYN>>>(out);
}